// round 5
// baseline (speedup 1.0000x reference)
#include <cuda_runtime.h>

// Modified Bessel K1(x) on (0.1, 10.1], matching the JAX fp32 A&S reference.
//   small(x) = (lg2(x)-1) * x * P1(x^2) + rcp(x) * P2(x^2)      [x <= 2]
//   large(x) = ex2(-0.5*lg2(x) - log2e*x) * P3(rcp(x))          [x > 2]
// Packed f32x2 math; polys Chebyshev-economized against the 1e-3 budget:
// P1 deg2, P2 deg3, P3 deg4 (worst-case pointwise err ~6e-4 at x=2).
// R5: V=4 front-batched loads (MLP_p1=4) with per-tile compute->store
// interleave to keep regs <= 40 (R4 was latency-limited: DRAM 78%, issue 69%).

typedef unsigned long long ull;

__device__ __forceinline__ ull f2(float lo, float hi) {
    ull d; asm("mov.b64 %0,{%1,%2};" : "=l"(d) : "f"(lo), "f"(hi)); return d;
}
__device__ __forceinline__ ull dup(float c) { return f2(c, c); }
__device__ __forceinline__ void unpack2(ull v, float& lo, float& hi) {
    asm("mov.b64 {%0,%1},%2;" : "=f"(lo), "=f"(hi) : "l"(v));
}
__device__ __forceinline__ ull ffma2(ull a, ull b, ull c) {
    ull d; asm("fma.rn.f32x2 %0,%1,%2,%3;" : "=l"(d) : "l"(a), "l"(b), "l"(c)); return d;
}
__device__ __forceinline__ ull fmul2(ull a, ull b) {
    ull d; asm("mul.rn.f32x2 %0,%1,%2;" : "=l"(d) : "l"(a), "l"(b)); return d;
}
__device__ __forceinline__ ull fadd2(ull a, ull b) {
    ull d; asm("add.rn.f32x2 %0,%1,%2;" : "=l"(d) : "l"(a), "l"(b)); return d;
}
__device__ __forceinline__ float rcpa(float x) {
    float y; asm("rcp.approx.f32 %0,%1;" : "=f"(y) : "f"(x)); return y;
}
__device__ __forceinline__ float lg2a(float x) {
    float y; asm("lg2.approx.f32 %0,%1;" : "=f"(y) : "f"(x)); return y;
}
__device__ __forceinline__ float ex2a(float x) {
    float y; asm("ex2.approx.f32 %0,%1;" : "=f"(y) : "f"(x)); return y;
}
__device__ __forceinline__ void ldg_cs2(const void* p, ull& a, ull& b) {
    asm("ld.global.cs.v2.u64 {%0,%1},[%2];" : "=l"(a), "=l"(b) : "l"(p));
}
__device__ __forceinline__ void stg_cs2(void* p, ull a, ull b) {
    asm("st.global.cs.v2.u64 [%0],{%1,%2};" :: "l"(p), "l"(a), "l"(b) : "memory");
}

__device__ __forceinline__ ull k1_pair2(ull x) {
    float x0, x1; unpack2(x, x0, x1);
    const ull r = f2(rcpa(x0), rcpa(x1));
    const ull L = f2(lg2a(x0), lg2a(x1));
    const ull s = fmul2(x, x);

    // P1(s): ln2 * I1_small refolded to s = x^2, economized to degree 2
    ull p1 = dup(2.0408281e-3f);
    p1 = ffma2(p1, s, dup(4.2966284e-2f));
    p1 = ffma2(p1, s, dup(0.34665256f));

    // P2(s): K1 small poly refolded to s = x^2, economized to degree 3
    ull p2 = dup(-3.4871707e-3f);
    p2 = ffma2(p2, s, dup(-4.0381576e-2f));
    p2 = ffma2(p2, s, dup(3.7256972e-2f));
    p2 = ffma2(p2, s, dup(1.0001701f));

    // P3(r): K1 large poly refolded to r = 1/x, economized to degree 4
    ull p3 = dup(-0.07165131f);
    p3 = ffma2(p3, r, dup(0.11351885f));
    p3 = ffma2(p3, r, dup(-0.14622480f));
    p3 = ffma2(p3, r, dup(0.46997238f));
    p3 = ffma2(p3, r, dup(1.25331414f));

    // small = (L - 1) * (x * P1) + r * P2
    const ull xp1 = fmul2(x, p1);
    const ull Lm1 = fadd2(L, dup(-1.0f));
    const ull small2 = ffma2(Lm1, xp1, fmul2(r, p2));

    // large = ex2(-0.5*L - log2e*x) * P3
    const ull earg = ffma2(L, dup(-0.5f), fmul2(x, dup(-1.44269504f)));
    float e0, e1; unpack2(earg, e0, e1);
    const ull large2 = fmul2(f2(ex2a(e0), ex2a(e1)), p3);

    float s0, s1, l0, l1;
    unpack2(small2, s0, s1);
    unpack2(large2, l0, l1);
    float y0 = (x0 <= 2.0f) ? s0 : l0;
    float y1 = (x1 <= 2.0f) ? s1 : l1;
    return f2(y0, y1);
}

static constexpr int TPB = 256;
static constexpr int V = 4;  // float4s per thread

// Full-tile kernel: 4 loads front-batched (MLP_p1=4), compute->store
// interleaved per tile to bound live registers.
__global__ void __launch_bounds__(TPB, 6) k1_main(const float4* __restrict__ in,
                                                  float4* __restrict__ out) {
    int i = blockIdx.x * (TPB * V) + threadIdx.x;
    ull a[V], b[V];
#pragma unroll
    for (int k = 0; k < V; k++)
        ldg_cs2(&in[i + k * TPB], a[k], b[k]);
#pragma unroll
    for (int k = 0; k < V; k++)
        stg_cs2(&out[i + k * TPB], k1_pair2(a[k]), k1_pair2(b[k]));
}

// Generic scalar tail for leftover elements (unused for 8192x8192).
__device__ __forceinline__ float k1_scalar(float x) {
    float r = rcpa(x), L = lg2a(x);
    float s = x * x;
    float p1 = 2.0408281e-3f;
    p1 = fmaf(p1, s, 4.2966284e-2f);
    p1 = fmaf(p1, s, 0.34665256f);
    float p2 = -3.4871707e-3f;
    p2 = fmaf(p2, s, -4.0381576e-2f);
    p2 = fmaf(p2, s, 3.7256972e-2f);
    p2 = fmaf(p2, s, 1.0001701f);
    float p3 = -0.07165131f;
    p3 = fmaf(p3, r, 0.11351885f);
    p3 = fmaf(p3, r, -0.14622480f);
    p3 = fmaf(p3, r, 0.46997238f);
    p3 = fmaf(p3, r, 1.25331414f);
    float small = fmaf(L - 1.0f, x * p1, r * p2);
    float large = ex2a(fmaf(-0.5f, L, -1.44269504f * x)) * p3;
    return (x <= 2.0f) ? small : large;
}

__global__ void k1_tail(const float* __restrict__ in, float* __restrict__ out,
                        int start, int n) {
    int i = start + blockIdx.x * blockDim.x + threadIdx.x;
    if (i < n) out[i] = k1_scalar(in[i]);
}

extern "C" void kernel_launch(void* const* d_in, const int* in_sizes, int n_in,
                              void* d_out, int out_size) {
    const float* x = (const float*)d_in[0];
    float* y = (float*)d_out;
    int n = in_sizes[0];

    int elems_per_block = TPB * V * 4;                   // 4096 elements
    int full_blocks = n / elems_per_block;
    if (full_blocks > 0) {
        k1_main<<<full_blocks, TPB>>>((const float4*)x, (float4*)y);
    }
    int done = full_blocks * elems_per_block;
    int rem = n - done;
    if (rem > 0) {
        int blocks = (rem + 255) / 256;
        k1_tail<<<blocks, 256>>>(x, y, done, n);
    }
}

// round 6
// speedup vs baseline: 1.1015x; 1.1015x over previous
#include <cuda_runtime.h>

// Modified Bessel K1(x) on (0.1, 10.1], matching the JAX fp32 A&S reference.
//   small(x) = (lg2(x)-1) * x * P1(x^2) + rcp(x) * P2(x^2)      [x <= 2]
//   large(x) = ex2(-0.5*lg2(x) - log2e*x) * P3(rcp(x))          [x > 2]
// Packed f32x2 polys, Chebyshev-economized (P1 deg2, P2 deg3, P3 deg4,
// rel_err ~1.3e-4 vs 1e-3 budget). 3 MUFU/elt.
// R6 = R4 structure (V=2, occ-first, regs<=32) + R5 economized polys +
// __ldcs/__stcs instead of forced-asm u64 moves (fewer ALU packs).

typedef unsigned long long ull;

__device__ __forceinline__ ull f2(float lo, float hi) {
    ull d; asm("mov.b64 %0,{%1,%2};" : "=l"(d) : "f"(lo), "f"(hi)); return d;
}
__device__ __forceinline__ ull dup(float c) { return f2(c, c); }
__device__ __forceinline__ void unpack2(ull v, float& lo, float& hi) {
    asm("mov.b64 {%0,%1},%2;" : "=f"(lo), "=f"(hi) : "l"(v));
}
__device__ __forceinline__ ull ffma2(ull a, ull b, ull c) {
    ull d; asm("fma.rn.f32x2 %0,%1,%2,%3;" : "=l"(d) : "l"(a), "l"(b), "l"(c)); return d;
}
__device__ __forceinline__ ull fmul2(ull a, ull b) {
    ull d; asm("mul.rn.f32x2 %0,%1,%2;" : "=l"(d) : "l"(a), "l"(b)); return d;
}
__device__ __forceinline__ ull fadd2(ull a, ull b) {
    ull d; asm("add.rn.f32x2 %0,%1,%2;" : "=l"(d) : "l"(a), "l"(b)); return d;
}
__device__ __forceinline__ float rcpa(float x) {
    float y; asm("rcp.approx.f32 %0,%1;" : "=f"(y) : "f"(x)); return y;
}
__device__ __forceinline__ float lg2a(float x) {
    float y; asm("lg2.approx.f32 %0,%1;" : "=f"(y) : "f"(x)); return y;
}
__device__ __forceinline__ float ex2a(float x) {
    float y; asm("ex2.approx.f32 %0,%1;" : "=f"(y) : "f"(x)); return y;
}

// Process one pair of elements; scalar in, scalar out (lets ptxas allocate
// register pairs for the packed ops without forced movs at boundaries).
__device__ __forceinline__ void k1_pair(float x0, float x1, float& y0, float& y1) {
    const ull x = f2(x0, x1);
    const ull r = f2(rcpa(x0), rcpa(x1));
    const ull L = f2(lg2a(x0), lg2a(x1));
    const ull s = fmul2(x, x);

    // P1(s): ln2 * I1_small refolded to s = x^2, economized to degree 2
    ull p1 = dup(2.0408281e-3f);
    p1 = ffma2(p1, s, dup(4.2966284e-2f));
    p1 = ffma2(p1, s, dup(0.34665256f));

    // P2(s): K1 small poly refolded to s = x^2, economized to degree 3
    ull p2 = dup(-3.4871707e-3f);
    p2 = ffma2(p2, s, dup(-4.0381576e-2f));
    p2 = ffma2(p2, s, dup(3.7256972e-2f));
    p2 = ffma2(p2, s, dup(1.0001701f));

    // P3(r): K1 large poly refolded to r = 1/x, economized to degree 4
    ull p3 = dup(-0.07165131f);
    p3 = ffma2(p3, r, dup(0.11351885f));
    p3 = ffma2(p3, r, dup(-0.14622480f));
    p3 = ffma2(p3, r, dup(0.46997238f));
    p3 = ffma2(p3, r, dup(1.25331414f));

    // small = (L - 1) * (x*P1) + r*P2
    const ull xp1 = fmul2(x, p1);
    const ull Lm1 = fadd2(L, dup(-1.0f));
    const ull small2 = ffma2(Lm1, xp1, fmul2(r, p2));

    // large = ex2(-0.5*L - log2e*x) * P3
    const ull earg = ffma2(L, dup(-0.5f), fmul2(x, dup(-1.44269504f)));
    float e0, e1; unpack2(earg, e0, e1);
    const ull large2 = fmul2(f2(ex2a(e0), ex2a(e1)), p3);

    float s0, s1, l0, l1;
    unpack2(small2, s0, s1);
    unpack2(large2, l0, l1);
    y0 = (x0 <= 2.0f) ? s0 : l0;
    y1 = (x1 <= 2.0f) ? s1 : l1;
}

static constexpr int TPB = 256;
static constexpr int V = 2;  // float4s per thread

__global__ void __launch_bounds__(TPB, 8) k1_main(const float4* __restrict__ in,
                                                  float4* __restrict__ out) {
    int i = blockIdx.x * (TPB * V) + threadIdx.x;
    float4 v0 = __ldcs(&in[i]);
    float4 v1 = __ldcs(&in[i + TPB]);
    float4 o0, o1;
    k1_pair(v0.x, v0.y, o0.x, o0.y);
    k1_pair(v0.z, v0.w, o0.z, o0.w);
    __stcs(&out[i], o0);
    k1_pair(v1.x, v1.y, o1.x, o1.y);
    k1_pair(v1.z, v1.w, o1.z, o1.w);
    __stcs(&out[i + TPB], o1);
}

// Generic scalar tail for leftover elements (unused for 8192x8192).
__device__ __forceinline__ float k1_scalar(float x) {
    float r = rcpa(x), L = lg2a(x);
    float s = x * x;
    float p1 = 2.0408281e-3f;
    p1 = fmaf(p1, s, 4.2966284e-2f);
    p1 = fmaf(p1, s, 0.34665256f);
    float p2 = -3.4871707e-3f;
    p2 = fmaf(p2, s, -4.0381576e-2f);
    p2 = fmaf(p2, s, 3.7256972e-2f);
    p2 = fmaf(p2, s, 1.0001701f);
    float p3 = -0.07165131f;
    p3 = fmaf(p3, r, 0.11351885f);
    p3 = fmaf(p3, r, -0.14622480f);
    p3 = fmaf(p3, r, 0.46997238f);
    p3 = fmaf(p3, r, 1.25331414f);
    float small = fmaf(L - 1.0f, x * p1, r * p2);
    float large = ex2a(fmaf(-0.5f, L, -1.44269504f * x)) * p3;
    return (x <= 2.0f) ? small : large;
}

__global__ void k1_tail(const float* __restrict__ in, float* __restrict__ out,
                        int start, int n) {
    int i = start + blockIdx.x * blockDim.x + threadIdx.x;
    if (i < n) out[i] = k1_scalar(in[i]);
}

extern "C" void kernel_launch(void* const* d_in, const int* in_sizes, int n_in,
                              void* d_out, int out_size) {
    const float* x = (const float*)d_in[0];
    float* y = (float*)d_out;
    int n = in_sizes[0];

    int elems_per_block = TPB * V * 4;                   // 2048 elements
    int full_blocks = n / elems_per_block;
    if (full_blocks > 0) {
        k1_main<<<full_blocks, TPB>>>((const float4*)x, (float4*)y);
    }
    int done = full_blocks * elems_per_block;
    int rem = n - done;
    if (rem > 0) {
        int blocks = (rem + 255) / 256;
        k1_tail<<<blocks, 256>>>(x, y, done, n);
    }
}